// round 8
// baseline (speedup 1.0000x reference)
#include <cuda_runtime.h>
#include <cstdint>
#include <math.h>

#define Bq   4
#define Nq   4096
#define Cq   256
#define DKq  64
#define NROWS (Bq*Nq)          // 16384
#define NEG_BIG (-3.402823466e38f)

__device__ float g_Qf[NROWS*DKq];
__device__ float g_Kf[NROWS*DKq];
__device__ float g_Qh[NROWS*DKq];
__device__ float g_Kh[NROWS*DKq];
__device__ int   g_cand[NROWS*64];      // 64 candidate cols per row

__device__ __forceinline__ void fma2(unsigned long long &acc,
                                     unsigned long long a, unsigned long long b) {
    asm volatile("fma.rn.f32x2 %0, %1, %2, %0;" : "+l"(acc) : "l"(a), "l"(b));
}
__device__ __forceinline__ float tf32_rna(float v) {
    uint32_t b;
    asm("cvt.rna.tf32.f32 %0, %1;" : "=r"(b) : "f"(v));
    return __uint_as_float(b);
}
__device__ __forceinline__ uint32_t smem_u32(const void* p) {
    uint32_t a;
    asm("{ .reg .u64 t; cvta.to.shared.u64 t, %1; cvt.u32.u64 %0, t; }" : "=r"(a) : "l"(p));
    return a;
}
__device__ __forceinline__ void cpa16(uint32_t dst, const void* src) {
    asm volatile("cp.async.cg.shared.global [%0], [%1], 16;" :: "r"(dst), "l"(src));
}

// =====================================================================
// Kernel 1: projections (exact fp32) + tf32-hi emit  (known-good)
// =====================================================================
#define XP 36

__global__ __launch_bounds__(256, 2) void proj_kernel(
        const float* __restrict__ x,
        const float* __restrict__ Wq,
        const float* __restrict__ Wk) {
    __shared__ float Xs[32*XP];
    __shared__ float Ws[128*XP];
    int t  = threadIdx.x;
    int rb = blockIdx.x;
    int b  = rb >> 7;
    int n0 = (rb & 127) << 5;
    int tx = t & 15, ty = t >> 4;

    unsigned long long acc[2][8];
#pragma unroll
    for (int i = 0; i < 2; i++)
#pragma unroll
        for (int j = 0; j < 8; j++) acc[i][j] = 0ull;

    const float* xb = x + (size_t)(b*Nq + n0) * Cq;

    for (int c0 = 0; c0 < Cq; c0 += 32) {
        {
            int r = t >> 3, cq = t & 7;
            float4 v = *(const float4*)(xb + (size_t)r*Cq + c0 + cq*4);
            *(float4*)(&Xs[r*XP + cq*4]) = v;
        }
#pragma unroll
        for (int s = 0; s < 16; s++) {
            int li  = t + s*256;
            int mat = li >> 11;
            int rem = li & 2047;
            int cc  = rem >> 6;
            int jj  = rem & 63;
            const float* W = mat ? Wk : Wq;
            Ws[(mat*64 + jj)*XP + cc] = W[(size_t)(c0+cc)*DKq + jj];
        }
        __syncthreads();
#pragma unroll
        for (int cc = 0; cc < 32; cc += 4) {
            ulonglong2 qv[2];
#pragma unroll
            for (int i = 0; i < 2; i++)
                qv[i] = *(const ulonglong2*)(&Xs[(ty + 16*i)*XP + cc]);
#pragma unroll
            for (int j = 0; j < 8; j++) {
                ulonglong2 wv = *(const ulonglong2*)(&Ws[(tx + 16*j)*XP + cc]);
#pragma unroll
                for (int i = 0; i < 2; i++) {
                    fma2(acc[i][j], qv[i].x, wv.x);
                    fma2(acc[i][j], qv[i].y, wv.y);
                }
            }
        }
        __syncthreads();
    }
#pragma unroll
    for (int i = 0; i < 2; i++) {
        size_t m = (size_t)rb*32 + ty + 16*i;
#pragma unroll
        for (int j = 0; j < 8; j++) {
            int col = tx + 16*j;
            union { unsigned long long u; float2 f; } cv; cv.u = acc[i][j];
            float v  = cv.f.x + cv.f.y;
            if (col < 64) {
                g_Qf[m*DKq + col] = v;
                g_Qh[m*DKq + col] = tf32_rna(v);
            } else {
                int k = col - 64;
                g_Kf[m*DKq + k] = v;
                g_Kh[m*DKq + k] = tf32_rna(v);
            }
        }
    }
}

// =====================================================================
// Kernel 2: approx tf32 GEMM + per-stream TOP-8 (deterministic guarantee)
//   grid 256: (128-row block) x (2048-key half). 512 threads, 16 warps.
//   warp = 16 rows (msub=wid>>1) x 64 keys (ksub=wid&1); step = 128 keys.
//   End: merge ksub stream pairs in smem -> 64 candidates/row.
// =====================================================================
#define QP     68
#define QPB    (QP*4)                   // 272 bytes
#define OFF_Q  0
#define QBYTES (128*QPB)                // 34816
#define OFF_B0 QBYTES
#define OFF_B1 (OFF_B0 + QBYTES)
#define SMEM_EDGE (OFF_B1 + QBYTES)     // 104448

__device__ __forceinline__ void mma8(float c[4], uint32_t a0, uint32_t a1,
                                     uint32_t a2, uint32_t a3,
                                     uint32_t b0, uint32_t b1) {
    asm volatile(
        "mma.sync.aligned.m16n8k8.row.col.f32.tf32.tf32.f32 "
        "{%0,%1,%2,%3},{%4,%5,%6,%7},{%8,%9},{%0,%1,%2,%3};"
        : "+f"(c[0]), "+f"(c[1]), "+f"(c[2]), "+f"(c[3])
        : "r"(a0), "r"(a1), "r"(a2), "r"(a3), "r"(b0), "r"(b1));
}

__device__ __forceinline__ void ins8(float* vals, int* idx, float v, int ci) {
    if (v > vals[7]) {
        float cv = v;
#pragma unroll
        for (int q = 0; q < 8; q++) {
            if (cv > vals[q]) {
                float tv = vals[q]; int ti = idx[q];
                vals[q] = cv; idx[q] = ci; cv = tv; ci = ti;
            }
        }
    }
}

__global__ __launch_bounds__(512)
void edge_kernel(float* __restrict__ out) {
    extern __shared__ __align__(16) char smem[];
    uint32_t sb = smem_u32(smem);
    const uint32_t* Qu = (const uint32_t*)(smem + OFF_Q);

    int tid = threadIdx.x;
    int wid = tid >> 5, lane = tid & 31;
    int g = lane >> 2, tg = lane & 3;
    int msub = wid >> 1, ksub = wid & 1;

    int bid  = blockIdx.x;
    int rb   = bid >> 1;
    int half = bid & 1;
    int m0    = rb * 128;
    int batch = rb >> 5;
    int key0  = half * 2048;

    // ---- load Q-hi tile (128 x 64) ----
    const float* qsrc = g_Qh + (size_t)m0 * DKq;
#pragma unroll
    for (int i = 0; i < 4; i++) {
        int idx = tid + i*512;              // 0..2047
        int r = idx >> 4, c = idx & 15;
        cpa16(sb + OFF_Q + (uint32_t)(r*QPB + c*16), qsrc + (size_t)r*DKq + c*4);
    }
    const float* gK = g_Kh + (size_t)batch * Nq * DKq;
#pragma unroll
    for (int i = 0; i < 4; i++) {
        int idx = tid + i*512;
        int r = idx >> 4, c = idx & 15;
        cpa16(sb + OFF_B0 + (uint32_t)(r*QPB + c*16),
              gK + (size_t)(key0 + r)*DKq + c*4);
    }
    asm volatile("cp.async.commit_group;");

    float vals[2][8]; int idx8[2][8];
#pragma unroll
    for (int l = 0; l < 2; l++)
#pragma unroll
        for (int q = 0; q < 8; q++) { vals[l][q] = NEG_BIG; idx8[l][q] = 0; }

    float4* out4 = (float4*)out;
    const float4 z4 = make_float4(0.f, 0.f, 0.f, 0.f);

    for (int step = 0; step < 16; step++) {
        const uint32_t* Bu = (const uint32_t*)(smem + ((step & 1) ? OFF_B1 : OFF_B0));
        if (step < 15) {
            uint32_t boff = (step & 1) ? OFF_B0 : OFF_B1;
            const float* src = gK + (size_t)(key0 + (step + 1)*128)*DKq;
#pragma unroll
            for (int i = 0; i < 4; i++) {
                int idx = tid + i*512;
                int r = idx >> 4, c = idx & 15;
                cpa16(sb + boff + (uint32_t)(r*QPB + c*16), src + (size_t)r*DKq + c*4);
            }
            asm volatile("cp.async.commit_group;");
            asm volatile("cp.async.wait_group 1;");
        } else {
            asm volatile("cp.async.wait_group 0;");
        }
        __syncthreads();

        // ---- streaming zero-fill: 128 output cols of this step ----
#pragma unroll
        for (int s = 0; s < 8; s++) {
            int idx = tid + s*512;          // 0..4095
            int r = idx >> 5, c = idx & 31;
            __stcs(&out4[(size_t)(m0 + r)*1024 + half*512 + step*32 + c], z4);
        }

        // ---- warp tf32 GEMM: 16 rows x 64 keys ----
        float c[8][4];
#pragma unroll
        for (int j = 0; j < 8; j++)
#pragma unroll
            for (int q = 0; q < 4; q++) c[j][q] = 0.f;

#pragma unroll
        for (int ks = 0; ks < 8; ks++) {
            int k0 = ks * 8;
            int rr = msub*16 + g;
            uint32_t a0 = Qu[rr*QP + k0 + tg];
            uint32_t a1 = Qu[(rr + 8)*QP + k0 + tg];
            uint32_t a2 = Qu[rr*QP + k0 + 4 + tg];
            uint32_t a3 = Qu[(rr + 8)*QP + k0 + 4 + tg];
#pragma unroll
            for (int j = 0; j < 8; j++) {
                int n = ksub*64 + j*8 + g;
                uint32_t b0 = Bu[n*QP + k0 + tg];
                uint32_t b1 = Bu[n*QP + k0 + 4 + tg];
                mma8(c[j], a0, a1, a2, a3, b0, b1);
            }
        }

        // ---- per-stream top-8 scan ----
#pragma unroll
        for (int j = 0; j < 8; j++) {
            int c0i = key0 + step*128 + ksub*64 + j*8 + 2*tg;
            ins8(vals[0], idx8[0], c[j][0], c0i);
            ins8(vals[0], idx8[0], c[j][1], c0i + 1);
            ins8(vals[1], idx8[1], c[j][2], c0i);
            ins8(vals[1], idx8[1], c[j][3], c0i + 1);
        }
        __syncthreads();
    }

    // ---- dump per-(row,tg,ksub) top-8 lists, merge ksub pairs -> 64 cand ----
    float* MV = (float*)smem;                 // [128*4][16]
    int*   MI = (int*)(smem + 32768);         // [128*4][16]
#pragma unroll
    for (int l = 0; l < 2; l++) {
        int rl = msub*16 + l*8 + g;
        int base = (rl*4 + tg)*16 + ksub*8;
#pragma unroll
        for (int q = 0; q < 8; q++) {
            MV[base + q] = vals[l][q];
            MI[base + q] = idx8[l][q];
        }
    }
    __syncthreads();
    {
        int rl = tid >> 2, t4 = tid & 3;      // 128 rows x 4 tg = 512 tasks
        const float* A  = &MV[(rl*4 + t4)*16];
        const int*   AI = &MI[(rl*4 + t4)*16];
        size_t base = (size_t)(m0 + rl)*64 + half*32 + t4*8;
        int pa = 0, pb = 8;
#pragma unroll
        for (int q = 0; q < 8; q++) {
            bool ta = (pa < 8) && (pb >= 16 || A[pa] >= A[pb]);
            int src = ta ? pa : pb;
            g_cand[base + q] = AI[src];
            if (ta) pa++; else pb++;
        }
    }
}

// =====================================================================
// Kernel 3: exact fp32 rescore (coalesced gather) + top-8 + softmax
// =====================================================================
__global__ __launch_bounds__(256) void rescore_kernel(float* __restrict__ out) {
    __shared__ float sd[8][64];
    int tid = threadIdx.x;
    int w = tid >> 5, lane = tid & 31;
    int row   = blockIdx.x*8 + w;
    int batch = row >> 12;
    int hl = lane & 15;

    const float* Kf = g_Kf + (size_t)batch * Nq * DKq;
    float4 qv = *(const float4*)(g_Qf + (size_t)row*DKq + hl*4);

    int c0 = g_cand[(size_t)row*64 + lane];
    int c1 = g_cand[(size_t)row*64 + 32 + lane];

#pragma unroll
    for (int it = 0; it < 32; it++) {
        int j = 2*it + (lane >> 4);
        int ca = __shfl_sync(0xFFFFFFFFu, c0, j & 31);
        int cb = __shfl_sync(0xFFFFFFFFu, c1, j & 31);
        int cnd = (it < 16) ? ca : cb;
        float4 kv = *(const float4*)(Kf + (size_t)cnd*DKq + hl*4);
        float p = qv.x*kv.x + qv.y*kv.y + qv.z*kv.z + qv.w*kv.w;
        p += __shfl_xor_sync(0xFFFFFFFFu, p, 1);
        p += __shfl_xor_sync(0xFFFFFFFFu, p, 2);
        p += __shfl_xor_sync(0xFFFFFFFFu, p, 4);
        p += __shfl_xor_sync(0xFFFFFFFFu, p, 8);
        if (hl == 0) sd[w][j] = p;
    }
    __syncwarp();

    float s0 = sd[w][lane];
    float s1 = sd[w][lane + 32];
    int   i0 = c0, i1 = c1;

    float bv[8]; int bi[8];
#pragma unroll
    for (int sel = 0; sel < 8; sel++) {
        float v; int ix;
        if (s0 > s1 || (s0 == s1 && i0 < i1)) { v = s0; ix = i0; }
        else                                  { v = s1; ix = i1; }
#pragma unroll
        for (int off = 16; off > 0; off >>= 1) {
            float vv = __shfl_xor_sync(0xFFFFFFFFu, v, off);
            int   ii = __shfl_xor_sync(0xFFFFFFFFu, ix, off);
            if (vv > v || (vv == v && ii < ix)) { v = vv; ix = ii; }
        }
        bv[sel] = v; bi[sel] = ix;
        if (i0 == ix) s0 = NEG_BIG;
        if (i1 == ix) s1 = NEG_BIG;
    }

    float mx = bv[0];
    float Z = 0.f, e[8];
#pragma unroll
    for (int q = 0; q < 8; q++) { e[q] = expf(0.125f*(bv[q] - mx)); Z += e[q]; }
    float inv = 1.0f / Z;
    if (lane < 8)
        out[(size_t)row*Nq + bi[lane]] = e[lane] * inv;
}

// =====================================================================
extern "C" void kernel_launch(void* const* d_in, const int* in_sizes, int n_in,
                              void* d_out, int out_size) {
    const float* x  = (const float*)d_in[0];
    const float* Wq = (const float*)d_in[1];
    const float* Wk = (const float*)d_in[2];
    float* out = (float*)d_out;

    cudaFuncSetAttribute(edge_kernel,
                         cudaFuncAttributeMaxDynamicSharedMemorySize, SMEM_EDGE);

    proj_kernel<<<NROWS/32, 256>>>(x, Wq, Wk);
    edge_kernel<<<NROWS/64, 512, SMEM_EDGE>>>(out);   // 256 CTAs
    rescore_kernel<<<NROWS/8, 256>>>(out);
}

// round 9
// speedup vs baseline: 2.3648x; 2.3648x over previous
#include <cuda_runtime.h>
#include <cstdint>
#include <math.h>

#define Bq   4
#define Nq   4096
#define Cq   256
#define DKq  64
#define NROWS (Bq*Nq)          // 16384
#define NEG_BIG (-3.402823466e38f)

__device__ float g_Qf[NROWS*DKq];
__device__ float g_Kf[NROWS*DKq];
__device__ float g_Qh[NROWS*DKq];
__device__ float g_Kh[NROWS*DKq];
__device__ int   g_cand[NROWS*64];      // 64 candidate cols per row

__device__ __forceinline__ void fma2(unsigned long long &acc,
                                     unsigned long long a, unsigned long long b) {
    asm volatile("fma.rn.f32x2 %0, %1, %2, %0;" : "+l"(acc) : "l"(a), "l"(b));
}
__device__ __forceinline__ float tf32_rna(float v) {
    uint32_t b;
    asm("cvt.rna.tf32.f32 %0, %1;" : "=r"(b) : "f"(v));
    return __uint_as_float(b);
}
__device__ __forceinline__ uint32_t smem_u32(const void* p) {
    uint32_t a;
    asm("{ .reg .u64 t; cvta.to.shared.u64 t, %1; cvt.u32.u64 %0, t; }" : "=r"(a) : "l"(p));
    return a;
}
__device__ __forceinline__ void cpa16(uint32_t dst, const void* src) {
    asm volatile("cp.async.cg.shared.global [%0], [%1], 16;" :: "r"(dst), "l"(src));
}
// pack column id into low 12 mantissa bits of score
__device__ __forceinline__ float packf(float v, int col) {
    return __uint_as_float((__float_as_uint(v) & ~0xFFFu) | (unsigned)col);
}

// =====================================================================
// Kernel 1: projections (exact fp32) + tf32-hi emit — known-good 51us
// =====================================================================
#define XP 36

__global__ __launch_bounds__(256) void proj_kernel(
        const float* __restrict__ x,
        const float* __restrict__ Wq,
        const float* __restrict__ Wk) {
    __shared__ float Xs[64*XP];
    __shared__ float Ws[128*XP];
    int t  = threadIdx.x;
    int rb = blockIdx.x;
    int b  = rb >> 6;
    int n0 = (rb & 63) << 6;
    int tx = t & 15, ty = t >> 4;

    unsigned long long acc[4][8];
#pragma unroll
    for (int i = 0; i < 4; i++)
#pragma unroll
        for (int j = 0; j < 8; j++) acc[i][j] = 0ull;

    const float* xb = x + (size_t)(b*Nq + n0) * Cq;

    for (int c0 = 0; c0 < Cq; c0 += 32) {
#pragma unroll
        for (int s = 0; s < 2; s++) {
            int li = t + s*256;
            int r = li >> 3, cq = li & 7;
            float4 v = *(const float4*)(xb + (size_t)r*Cq + c0 + cq*4);
            *(float4*)(&Xs[r*XP + cq*4]) = v;
        }
#pragma unroll
        for (int s = 0; s < 16; s++) {
            int li  = t + s*256;
            int mat = li >> 11;
            int rem = li & 2047;
            int cc  = rem >> 6;
            int jj  = rem & 63;
            const float* W = mat ? Wk : Wq;
            Ws[(mat*64 + jj)*XP + cc] = W[(size_t)(c0+cc)*DKq + jj];
        }
        __syncthreads();
#pragma unroll
        for (int cc = 0; cc < 32; cc += 4) {
            ulonglong2 qv[4];
#pragma unroll
            for (int i = 0; i < 4; i++)
                qv[i] = *(const ulonglong2*)(&Xs[(ty + 16*i)*XP + cc]);
#pragma unroll
            for (int j = 0; j < 8; j++) {
                ulonglong2 wv = *(const ulonglong2*)(&Ws[(tx + 16*j)*XP + cc]);
#pragma unroll
                for (int i = 0; i < 4; i++) {
                    fma2(acc[i][j], qv[i].x, wv.x);
                    fma2(acc[i][j], qv[i].y, wv.y);
                }
            }
        }
        __syncthreads();
    }
#pragma unroll
    for (int i = 0; i < 4; i++) {
        size_t m = (size_t)rb*64 + ty + 16*i;
#pragma unroll
        for (int j = 0; j < 8; j++) {
            int col = tx + 16*j;
            union { unsigned long long u; float2 f; } cv; cv.u = acc[i][j];
            float v  = cv.f.x + cv.f.y;
            if (col < 64) {
                g_Qf[m*DKq + col] = v;
                g_Qh[m*DKq + col] = tf32_rna(v);
            } else {
                int k = col - 64;
                g_Kf[m*DKq + k] = v;
                g_Kh[m*DKq + k] = tf32_rna(v);
            }
        }
    }
}

// =====================================================================
// Kernel 2: approx tf32 GEMM + per-stream top-8 (index-packed scores)
//   grid 256 CTAs: 64 query rows each, ALL 4096 keys, step = 128 keys.
//   256 threads / 8 warps; warp = 16 rows (msub=wid>>1) x 64 keys (ksub).
//   2 CTAs/SM (87KB smem, ~90 regs). 8 streams/row x top-8 = 64 cand/row.
// =====================================================================
#define QP     68
#define QPB    (QP*4)                   // 272 bytes
#define OFF_Q  0
#define QBYTES (64*QPB)                 // 17408
#define OFF_B0 QBYTES
#define BBYTES (128*QPB)                // 34816
#define OFF_B1 (OFF_B0 + BBYTES)
#define SMEM_EDGE (OFF_B1 + BBYTES)     // 87040

__device__ __forceinline__ void mma8(float c[4], uint32_t a0, uint32_t a1,
                                     uint32_t a2, uint32_t a3,
                                     uint32_t b0, uint32_t b1) {
    asm volatile(
        "mma.sync.aligned.m16n8k8.row.col.f32.tf32.tf32.f32 "
        "{%0,%1,%2,%3},{%4,%5,%6,%7},{%8,%9},{%0,%1,%2,%3};"
        : "+f"(c[0]), "+f"(c[1]), "+f"(c[2]), "+f"(c[3])
        : "r"(a0), "r"(a1), "r"(a2), "r"(a3), "r"(b0), "r"(b1));
}

__device__ __forceinline__ void ins8p(float* vals, float v, int col) {
    if (v > vals[7]) {                  // raw-vs-packed compare: 2^-12 slack, safe
        float pv = packf(v, col);
#pragma unroll
        for (int q = 0; q < 8; q++) {
            if (pv > vals[q]) { float tv = vals[q]; vals[q] = pv; pv = tv; }
        }
    }
}

__global__ __launch_bounds__(256, 2)
void edge_kernel(float* __restrict__ out) {
    extern __shared__ __align__(16) char smem[];
    uint32_t sb = smem_u32(smem);
    const uint32_t* Qu = (const uint32_t*)(smem + OFF_Q);

    int tid = threadIdx.x;
    int wid = tid >> 5, lane = tid & 31;
    int g = lane >> 2, tg = lane & 3;
    int msub = wid >> 1, ksub = wid & 1;

    int m0    = blockIdx.x * 64;
    int batch = blockIdx.x >> 6;            // 64 CTAs per batch

    // ---- load Q-hi tile (64 x 64): 4 float4/thread ----
    const float* qsrc = g_Qh + (size_t)m0 * DKq;
#pragma unroll
    for (int i = 0; i < 4; i++) {
        int idx = tid + i*256;              // 0..1023
        int r = idx >> 4, c = idx & 15;
        cpa16(sb + OFF_Q + (uint32_t)(r*QPB + c*16), qsrc + (size_t)r*DKq + c*4);
    }
    const float* gK = g_Kh + (size_t)batch * Nq * DKq;
    // prefetch step 0 (128 keys): 8 float4/thread
#pragma unroll
    for (int i = 0; i < 8; i++) {
        int idx = tid + i*256;              // 0..2047
        int r = idx >> 4, c = idx & 15;
        cpa16(sb + OFF_B0 + (uint32_t)(r*QPB + c*16), gK + (size_t)r*DKq + c*4);
    }
    asm volatile("cp.async.commit_group;");

    float vals[2][8];
#pragma unroll
    for (int l = 0; l < 2; l++)
#pragma unroll
        for (int q = 0; q < 8; q++) vals[l][q] = NEG_BIG;

    float4* out4 = (float4*)out;
    const float4 z4 = make_float4(0.f, 0.f, 0.f, 0.f);

    for (int step = 0; step < 32; step++) {
        const uint32_t* Bu = (const uint32_t*)(smem + ((step & 1) ? OFF_B1 : OFF_B0));
        if (step < 31) {
            uint32_t boff = (step & 1) ? OFF_B0 : OFF_B1;
            const float* src = gK + (size_t)(step + 1)*128*DKq;
#pragma unroll
            for (int i = 0; i < 8; i++) {
                int idx = tid + i*256;
                int r = idx >> 4, c = idx & 15;
                cpa16(sb + boff + (uint32_t)(r*QPB + c*16), src + (size_t)r*DKq + c*4);
            }
            asm volatile("cp.async.commit_group;");
            asm volatile("cp.async.wait_group 1;");
        } else {
            asm volatile("cp.async.wait_group 0;");
        }
        __syncthreads();

        // ---- streaming zero-fill: this step's 128 output cols, 64 rows ----
#pragma unroll
        for (int s = 0; s < 8; s++) {
            int idx = tid + s*256;          // 0..2047
            int r = idx >> 5, c = idx & 31;
            __stcs(&out4[(size_t)(m0 + r)*1024 + step*32 + c], z4);
        }

        // ---- warp tf32 GEMM: 16 rows x 64 keys ----
        float c[8][4];
#pragma unroll
        for (int j = 0; j < 8; j++)
#pragma unroll
            for (int q = 0; q < 4; q++) c[j][q] = 0.f;

#pragma unroll
        for (int ks = 0; ks < 8; ks++) {
            int k0 = ks * 8;
            int rr = msub*16 + g;
            uint32_t a0 = Qu[rr*QP + k0 + tg];
            uint32_t a1 = Qu[(rr + 8)*QP + k0 + tg];
            uint32_t a2 = Qu[rr*QP + k0 + 4 + tg];
            uint32_t a3 = Qu[(rr + 8)*QP + k0 + 4 + tg];
#pragma unroll
            for (int j = 0; j < 8; j++) {
                int n = ksub*64 + j*8 + g;
                uint32_t b0 = Bu[n*QP + k0 + tg];
                uint32_t b1 = Bu[n*QP + k0 + 4 + tg];
                mma8(c[j], a0, a1, a2, a3, b0, b1);
            }
        }

        // ---- per-stream top-8 scan (packed) ----
#pragma unroll
        for (int j = 0; j < 8; j++) {
            int c0i = step*128 + ksub*64 + j*8 + 2*tg;
            ins8p(vals[0], c[j][0], c0i);
            ins8p(vals[0], c[j][1], c0i + 1);
            ins8p(vals[1], c[j][2], c0i);
            ins8p(vals[1], c[j][3], c0i + 1);
        }
        __syncthreads();
    }

    // ---- dump candidates: row streams (g, g+8), slot (ksub*4+tg)*8 ----
#pragma unroll
    for (int l = 0; l < 2; l++) {
        int row = m0 + msub*16 + l*8 + g;
        size_t base = (size_t)row*64 + (ksub*4 + tg)*8;
#pragma unroll
        for (int q = 0; q < 8; q++)
            g_cand[base + q] = (int)(__float_as_uint(vals[l][q]) & 0xFFFu);
    }
}

// =====================================================================
// Kernel 3: exact fp32 rescore (coalesced gather) + top-8 + softmax
// =====================================================================
__global__ __launch_bounds__(256) void rescore_kernel(float* __restrict__ out) {
    __shared__ float sd[8][64];
    int tid = threadIdx.x;
    int w = tid >> 5, lane = tid & 31;
    int row   = blockIdx.x*8 + w;
    int batch = row >> 12;
    int hl = lane & 15;

    const float* Kf = g_Kf + (size_t)batch * Nq * DKq;
    float4 qv = *(const float4*)(g_Qf + (size_t)row*DKq + hl*4);

    int c0 = g_cand[(size_t)row*64 + lane];
    int c1 = g_cand[(size_t)row*64 + 32 + lane];

#pragma unroll
    for (int it = 0; it < 32; it++) {
        int j = 2*it + (lane >> 4);
        int ca = __shfl_sync(0xFFFFFFFFu, c0, j & 31);
        int cb = __shfl_sync(0xFFFFFFFFu, c1, j & 31);
        int cnd = (it < 16) ? ca : cb;
        float4 kv = *(const float4*)(Kf + (size_t)cnd*DKq + hl*4);
        float p = qv.x*kv.x + qv.y*kv.y + qv.z*kv.z + qv.w*kv.w;
        p += __shfl_xor_sync(0xFFFFFFFFu, p, 1);
        p += __shfl_xor_sync(0xFFFFFFFFu, p, 2);
        p += __shfl_xor_sync(0xFFFFFFFFu, p, 4);
        p += __shfl_xor_sync(0xFFFFFFFFu, p, 8);
        if (hl == 0) sd[w][j] = p;
    }
    __syncwarp();

    float s0 = sd[w][lane];
    float s1 = sd[w][lane + 32];
    int   i0 = c0, i1 = c1;

    float bv[8]; int bi[8];
#pragma unroll
    for (int sel = 0; sel < 8; sel++) {
        float v; int ix;
        if (s0 > s1 || (s0 == s1 && i0 < i1)) { v = s0; ix = i0; }
        else                                  { v = s1; ix = i1; }
#pragma unroll
        for (int off = 16; off > 0; off >>= 1) {
            float vv = __shfl_xor_sync(0xFFFFFFFFu, v, off);
            int   ii = __shfl_xor_sync(0xFFFFFFFFu, ix, off);
            if (vv > v || (vv == v && ii < ix)) { v = vv; ix = ii; }
        }
        bv[sel] = v; bi[sel] = ix;
        if (i0 == ix) s0 = NEG_BIG;
        if (i1 == ix) s1 = NEG_BIG;
    }

    float mx = bv[0];
    float Z = 0.f, e[8];
#pragma unroll
    for (int q = 0; q < 8; q++) { e[q] = expf(0.125f*(bv[q] - mx)); Z += e[q]; }
    float inv = 1.0f / Z;
    if (lane < 8)
        out[(size_t)row*Nq + bi[lane]] = e[lane] * inv;
}

// =====================================================================
extern "C" void kernel_launch(void* const* d_in, const int* in_sizes, int n_in,
                              void* d_out, int out_size) {
    const float* x  = (const float*)d_in[0];
    const float* Wq = (const float*)d_in[1];
    const float* Wk = (const float*)d_in[2];
    float* out = (float*)d_out;

    cudaFuncSetAttribute(edge_kernel,
                         cudaFuncAttributeMaxDynamicSharedMemorySize, SMEM_EDGE);

    proj_kernel<<<NROWS/64, 256>>>(x, Wq, Wk);
    edge_kernel<<<NROWS/64, 256, SMEM_EDGE>>>(out);   // 256 CTAs
    rescore_kernel<<<NROWS/8, 256>>>(out);
}